// round 7
// baseline (speedup 1.0000x reference)
#include <cuda_runtime.h>

#define B 512
#define N 512
#define NB 512
#define FULL 0xffffffffu

// Cross-block accumulators (zero at load; finalizer resets for graph replay).
__device__ double             g_sum   = 0.0;
__device__ unsigned long long g_pairs = 0ULL;
__device__ unsigned int       g_done  = 0u;

// Monotone non-decreasing float -> bucket. Clamped ends are safe: the query
// checks the threshold's own bucket exactly.
__device__ __forceinline__ int bucket_of(float q) {
    float f = (q + 8.0f) * 32.0f;
    f = fminf(fmaxf(f, 0.0f), 511.0f);
    return (int)f;
}

__global__ void __launch_bounds__(32)
row_kernel(const float* __restrict__ scores,
           const unsigned int* __restrict__ labels,
           float* __restrict__ out) {
    __shared__ int   s_cnt[NB];        // histogram -> scatter cursors
    __shared__ float s_sum[NB];        // per-bucket sum
    __shared__ int   s_scnt[NB + 4];   // S_cnt[b] = count(bucket >= b); S[512]=0
    __shared__ float s_ssum[NB + 4];   // S_sum[b] = sum  (bucket >= b)
    __shared__ float s_scat[N];        // negs, descending-bucket order

    const int row  = blockIdx.x;
    const int lane = threadIdx.x;

    // ---- zero histogram (vectorized, conflict-free)
    const int4   zi = make_int4(0, 0, 0, 0);
    const float4 zf = make_float4(0.f, 0.f, 0.f, 0.f);
    #pragma unroll
    for (int k = 0; k < 4; k++) {
        ((int4*)s_cnt)[lane + 32 * k]   = zi;
        ((float4*)s_sum)[lane + 32 * k] = zf;
    }

    // ---- dtype detect: odd words of the first 1KB all-zero <=> int64 labels
    unsigned int pr = 0u;
    #pragma unroll
    for (int k = 0; k < 8; k++) pr |= labels[2 * (lane + 32 * k) + 1];
    const unsigned int any_odd = __ballot_sync(FULL, pr != 0u);
    const int stride = any_odd ? 1 : 2;

    // ---- vectorized row loads: 16 elements/lane (order within row irrelevant)
    float4 sv[4];
    const float4* s4 = (const float4*)(scores + (size_t)row * N);
    #pragma unroll
    for (int k = 0; k < 4; k++) sv[k] = s4[lane + 32 * k];

    uint4 lv[4];
    if (stride == 1) {
        const uint4* l4 = (const uint4*)(labels + (size_t)row * N);
        #pragma unroll
        for (int k = 0; k < 4; k++) lv[k] = l4[lane + 32 * k];
    } else {
        const uint4* l8 = (const uint4*)(labels + (size_t)row * N * 2);
        #pragma unroll
        for (int k = 0; k < 4; k++) {
            uint4 a = l8[2 * (lane + 32 * k)];
            uint4 b = l8[2 * (lane + 32 * k) + 1];
            lv[k] = make_uint4(a.x, a.z, b.x, b.z);   // low words (values 0/1)
        }
    }

    float v[16];
    unsigned int negm = 0u;                 // bit e set <=> element e is negative
    #pragma unroll
    for (int k = 0; k < 4; k++) {
        v[4 * k + 0] = sv[k].x; v[4 * k + 1] = sv[k].y;
        v[4 * k + 2] = sv[k].z; v[4 * k + 3] = sv[k].w;
        if (lv[k].x == 0u) negm |= 1u << (4 * k + 0);
        if (lv[k].y == 0u) negm |= 1u << (4 * k + 1);
        if (lv[k].z == 0u) negm |= 1u << (4 * k + 2);
        if (lv[k].w == 0u) negm |= 1u << (4 * k + 3);
    }
    __syncwarp();                           // zeroing visible before atomics

    // ---- histogram of negatives
    #pragma unroll
    for (int e = 0; e < 16; e++) {
        if (negm & (1u << e)) {
            int b = bucket_of(v[e]);
            atomicAdd(&s_cnt[b], 1);
            atomicAdd(&s_sum[b], v[e]);
        }
    }
    __syncwarp();

    // ---- suffix "scan": lane owns buckets [16*lane, 16*lane+16)
    int   c[16]; float m[16];
    #pragma unroll
    for (int k = 0; k < 4; k++) {
        int4   ci = ((const int4*)s_cnt)[4 * lane + k];
        float4 mi = ((const float4*)s_sum)[4 * lane + k];
        c[4*k+0] = ci.x; c[4*k+1] = ci.y; c[4*k+2] = ci.z; c[4*k+3] = ci.w;
        m[4*k+0] = mi.x; m[4*k+1] = mi.y; m[4*k+2] = mi.z; m[4*k+3] = mi.w;
    }
    int ic[16]; float im[16];               // inclusive-from-high local suffix
    {
        int rc = 0; float rm = 0.f;
        #pragma unroll
        for (int i = 15; i >= 0; i--) { rc += c[i]; rm += m[i]; ic[i] = rc; im[i] = rm; }
    }
    const int totc = ic[0]; const float totm = im[0];
    int sc = totc; float sm = totm;         // inclusive suffix across lanes
    #pragma unroll
    for (int o = 1; o < 32; o <<= 1) {
        int   a = __shfl_down_sync(FULL, sc, o);
        float b = __shfl_down_sync(FULL, sm, o);
        if (lane + o < 32) { sc += a; sm += b; }
    }
    const int   exc = sc - totc;            // strictly-higher lanes
    const float exm = sm - totm;
    __syncwarp();                           // all reads of s_cnt done before overwrite
    #pragma unroll
    for (int k = 0; k < 4; k++) {           // S arrays (vectorized stores)
        ((int4*)s_scnt)[4 * lane + k] = make_int4(
            exc + ic[4*k+0], exc + ic[4*k+1], exc + ic[4*k+2], exc + ic[4*k+3]);
        ((float4*)s_ssum)[4 * lane + k] = make_float4(
            exm + im[4*k+0], exm + im[4*k+1], exm + im[4*k+2], exm + im[4*k+3]);
    }
    #pragma unroll
    for (int k = 0; k < 4; k++) {           // cursor[b] = S[b+1]
        int n0 = exc + ic[4*k+1];
        int n1 = exc + ic[4*k+2];
        int n2 = exc + ic[4*k+3];
        int n3 = (k < 3) ? exc + ic[4*k+4] : exc;
        ((int4*)s_cnt)[4 * lane + k] = make_int4(n0, n1, n2, n3);
    }
    if (lane == 31) { s_scnt[512] = 0; s_ssum[512] = 0.f; }
    __syncwarp();

    // ---- counting-sort scatter of negatives (descending bucket order)
    #pragma unroll
    for (int e = 0; e < 16; e++) {
        if (negm & (1u << e)) {
            int b = bucket_of(v[e]);
            s_scat[atomicAdd(&s_cnt[b], 1)] = v[e];
        }
    }
    __syncwarp();

    // ---- per-pos queries (positives sit in this lane's registers)
    float acc = 0.0f;
    #pragma unroll
    for (int e = 0; e < 16; e++) {
        if (!(negm & (1u << e))) {
            float p = v[e];
            float t = p - 1.0f;
            int b = bucket_of(t);
            int st = s_scnt[b + 1];         // segment [S[b+1], S[b]) = bucket b
            int en = s_scnt[b];
            float cg = (float)st;           // count(bucket > b) => q > t
            float sg = s_ssum[b + 1];
            for (int j = st; j < en; j++) { // exact scan of threshold bucket
                float q = s_scat[j];
                if (q > t) { cg += 1.0f; sg += q; }
            }
            acc += cg * (1.0f - p) + sg;
        }
    }

    // ---- warp reduce (loss + npos), then global accumulate
    int nposl = __popc(~negm & 0xFFFFu);
    #pragma unroll
    for (int o = 16; o > 0; o >>= 1) {
        acc   += __shfl_down_sync(FULL, acc, o);
        nposl += __shfl_down_sync(FULL, nposl, o);
    }
    if (lane == 0) {
        const int npos = nposl, nneg = N - nposl;
        atomicAdd(&g_sum, (double)acc);
        atomicAdd(&g_pairs, (unsigned long long)npos * (unsigned long long)nneg);
        __threadfence();
        unsigned int ticket = atomicAdd(&g_done, 1u);
        if (ticket == B - 1) {              // last warp: everything is visible
            __threadfence();
            double    s  = atomicAdd(&g_sum, 0.0);
            long long np = (long long)atomicAdd(&g_pairs, 0ULL);
            out[0] = (np > 0) ? (float)(s / (double)np) : 0.0f;
            g_sum   = 0.0;                  // reset for next graph replay
            g_pairs = 0ULL;
            __threadfence();
            g_done  = 0u;
        }
    }
}

extern "C" void kernel_launch(void* const* d_in, const int* in_sizes, int n_in,
                              void* d_out, int out_size) {
    const float*        scores = (const float*)d_in[0];
    const unsigned int* labels = (const unsigned int*)d_in[1];
    float*              out    = (float*)d_out;

    row_kernel<<<B, 32>>>(scores, labels, out);
}

// round 10
// speedup vs baseline: 1.5761x; 1.5761x over previous
#include <cuda_runtime.h>

#define B 512
#define N 512
#define NB 512
#define THREADS 256
#define FULL 0xffffffffu

// Cross-block accumulators (zero at load; last block resets for graph replay).
__device__ double             g_sum   = 0.0;
__device__ unsigned long long g_pairs = 0ULL;
__device__ unsigned int       g_done  = 0u;

// Monotone non-decreasing float -> bucket. Clamped ends are safe: the query
// exact-scans the threshold's own bucket.
__device__ __forceinline__ int bucket_of(float q) {
    float f = (q + 8.0f) * 32.0f;
    f = fminf(fmaxf(f, 0.0f), 511.0f);
    return (int)f;
}

__global__ void __launch_bounds__(THREADS)
fused_kernel(const float* __restrict__ scores,
             const unsigned int* __restrict__ labels,
             float* __restrict__ out) {
    __shared__ int   s_cnt[NB];        // histogram counts
    __shared__ float s_sum[NB];        // histogram sums
    __shared__ int   s_scnt[NB + 2];   // S[b] = count(bucket >= b); S[512] = 0
    __shared__ float s_ssum[NB + 2];   // Sm[b] = sum(bucket >= b)
    __shared__ int   s_cur[NB];        // scatter cursors (= S[b+1])
    __shared__ float s_scat[N];        // negs in descending-bucket order
    __shared__ int   s_gtc[8];         // per-warp bucket-group count totals
    __shared__ float s_gts[8];         // per-warp bucket-group sum totals
    __shared__ float s_redf[8];
    __shared__ int   s_redi[8];

    const int row  = blockIdx.x;
    const int tid  = threadIdx.x;
    const int lane = tid & 31;
    const int wrp  = tid >> 5;

    // ---- zero histogram; issue probe + score loads before the bar (scores
    // are stride-independent, so their DRAM latency overlaps detection)
    s_cnt[tid] = 0;  s_cnt[tid + 256] = 0;
    s_sum[tid] = 0.f; s_sum[tid + 256] = 0.f;
    const unsigned int probe = labels[2 * tid + 1];
    const float* srow = scores + (size_t)row * N;
    const float q0 = srow[tid];
    const float q1 = srow[tid + 256];

    const int any_odd = __syncthreads_or(probe != 0u);        // bar 1
    const int stride = any_odd ? 1 : 2;                       // words per label

    const unsigned int* lrow = labels + (size_t)row * N * stride;
    const unsigned int u0 = lrow[(size_t)tid * stride];
    const unsigned int u1 = lrow[(size_t)(tid + 256) * stride];
    const bool neg0 = (u0 == 0u);
    const bool neg1 = (u1 == 0u);
    const int  b0 = bucket_of(q0);
    const int  b1 = bucket_of(q1);

    // ---- histogram of negatives
    if (neg0) { atomicAdd(&s_cnt[b0], 1); atomicAdd(&s_sum[b0], q0); }
    if (neg1) { atomicAdd(&s_cnt[b1], 1); atomicAdd(&s_sum[b1], q1); }
    __syncthreads();                                          // bar 2

    // ---- suffix scan; lane owns contiguous buckets {2*tid, 2*tid+1}
    const int2   ci = ((const int2*)s_cnt)[tid];
    const float2 mi = ((const float2*)s_sum)[tid];
    const int   c0 = ci.x,  c1 = ci.y;
    const float m0 = mi.x,  m1 = mi.y;
    const int   tot  = c0 + c1;
    const float totm = m0 + m1;

    int   sc = tot;   float sm = totm;    // inclusive suffix over lanes >= lane
    #pragma unroll
    for (int o = 1; o < 32; o <<= 1) {
        int   a = __shfl_down_sync(FULL, sc, o);
        float b = __shfl_down_sync(FULL, sm, o);
        if (lane + o < 32) { sc += a; sm += b; }
    }
    if (lane == 0) { s_gtc[wrp] = sc; s_gts[wrp] = sm; }      // warp totals
    __syncthreads();                                          // bar 3

    int   Wc = 0; float Wm = 0.f;         // totals of higher warps
    for (int g = wrp + 1; g < 8; g++) { Wc += s_gtc[g]; Wm += s_gts[g]; }
    const int   T  = (sc - tot)  + Wc;    // suffix strictly above bucket 2t+1
    const float Tm = (sm - totm) + Wm;

    // S[2t] = c0+c1+T, S[2t+1] = c1+T; cursor[2t] = S[2t+1], cursor[2t+1] = T
    ((int2*)s_scnt)[tid]   = make_int2(tot + T, c1 + T);
    ((float2*)s_ssum)[tid] = make_float2(totm + Tm, m1 + Tm);
    ((int2*)s_cur)[tid]    = make_int2(c1 + T, T);
    if (tid == 255) { s_scnt[512] = 0; s_ssum[512] = 0.f; }
    __syncthreads();                                          // bar 4

    // ---- counting-sort scatter of negatives (descending bucket order)
    if (neg0) s_scat[atomicAdd(&s_cur[b0], 1)] = q0;
    if (neg1) s_scat[atomicAdd(&s_cur[b1], 1)] = q1;
    __syncthreads();                                          // bar 5

    // ---- queries straight from registers (no pos compaction)
    float acc = 0.0f;
    #pragma unroll
    for (int e = 0; e < 2; e++) {
        const bool  isneg = e ? neg1 : neg0;
        const float p     = e ? q1   : q0;
        if (!isneg) {
            const float t = p - 1.0f;
            const int   b = bucket_of(t);
            const int  st = s_scnt[b + 1];     // count(bucket > b): all > t
            const int  en = s_scnt[b];
            float cg = (float)st;
            float sg = s_ssum[b + 1];
            for (int j = st; j < en; j++) {    // exact scan of bucket b
                const float q = s_scat[j];
                if (q > t) { cg += 1.0f; sg += q; }
            }
            acc += cg * (1.0f - p) + sg;
        }
    }

    // ---- reduce loss + npos
    int nposl = (neg0 ? 0 : 1) + (neg1 ? 0 : 1);
    #pragma unroll
    for (int o = 16; o > 0; o >>= 1) {
        acc   += __shfl_down_sync(FULL, acc, o);
        nposl += __shfl_down_sync(FULL, nposl, o);
    }
    if (lane == 0) { s_redf[wrp] = acc; s_redi[wrp] = nposl; }
    __syncthreads();                                          // bar 6

    // ---- single-level cross-block accumulate + last-block finalize
    if (tid == 0) {
        float vsum = 0.0f; int npos = 0;
        #pragma unroll
        for (int w = 0; w < 8; w++) { vsum += s_redf[w]; npos += s_redi[w]; }
        const int nneg = N - npos;

        atomicAdd(&g_sum, (double)vsum);
        atomicAdd(&g_pairs, (unsigned long long)npos * (unsigned long long)nneg);
        __threadfence();
        unsigned int ticket = atomicAdd(&g_done, 1u);
        if (ticket == B - 1) {
            __threadfence();
            double    s  = atomicAdd(&g_sum, 0.0);
            long long np = (long long)atomicAdd(&g_pairs, 0ULL);
            out[0] = (np > 0) ? (float)(s / (double)np) : 0.0f;
            g_sum   = 0.0;
            g_pairs = 0ULL;
            __threadfence();
            g_done  = 0u;
        }
    }
}

extern "C" void kernel_launch(void* const* d_in, const int* in_sizes, int n_in,
                              void* d_out, int out_size) {
    const float*        scores = (const float*)d_in[0];
    const unsigned int* labels = (const unsigned int*)d_in[1];
    float*              out    = (float*)d_out;

    fused_kernel<<<B, THREADS>>>(scores, labels, out);
}